// round 1
// baseline (speedup 1.0000x reference)
#include <cuda_runtime.h>
#include <math.h>

#define NTOK 9216
#define BATCH 4
#define CHN 256
#define HEADS 8
#define DH 32
#define NB 128
#define BH (BATCH*HEADS)      // 32
#define MTOT (BATCH*NTOK)     // 36864

#define DN 0.4204482076268573f        // 32^-0.25
#define HALF_DN2 0.08838834764831845f // 0.5 * 32^-0.5
#define RATIO 0.08838834764831845f    // 128^-0.5
#define FEPS 1e-4f

static __device__ float d_q[MTOT*CHN];
static __device__ float d_k[MTOT*CHN];
static __device__ float d_v[MTOT*CHN];
static __device__ float d_kdash[(size_t)BH*NTOK*NB];   // stores dash - diag
static __device__ float d_kmax[BH];
static __device__ float d_ksum[BH*NB];
static __device__ float d_ctx[BH*NB*DH];
static __device__ float d_attn[MTOT*CHN];
static __device__ float d_wcomb[CHN*CHN];
static __device__ float d_bcomb[CHN];

__device__ __forceinline__ void atomicMaxFloat(float* addr, float val) {
    int* ai = (int*)addr;
    int old = __float_as_int(*addr);
    while (__int_as_float(old) < val) {
        int assumed = old;
        old = atomicCAS(ai, assumed, __float_as_int(val));
        if (old == assumed) break;
    }
}

// ---------------------------------------------------------------------------
// init: zero ctx/ksum, kmax = -inf
// ---------------------------------------------------------------------------
__global__ void init_k() {
    int i = blockIdx.x * 256 + threadIdx.x;
    if (i < BH*NB*DH) d_ctx[i] = 0.0f;
    if (i < BH*NB)    d_ksum[i] = 0.0f;
    if (i < BH)       d_kmax[i] = -INFINITY;
}

// ---------------------------------------------------------------------------
// combined weight: wcomb = wp @ wo ; bcomb = wp @ bo + bp
// ---------------------------------------------------------------------------
__global__ __launch_bounds__(256) void wcomb_k(const float* __restrict__ wo,
                                               const float* __restrict__ bo,
                                               const float* __restrict__ wp,
                                               const float* __restrict__ bp) {
    int o = blockIdx.x;
    int c = threadIdx.x;
    float acc = 0.0f;
    for (int j = 0; j < CHN; j++) acc += wp[o*CHN + j] * wo[j*CHN + c];
    d_wcomb[o*CHN + c] = acc;
    if (c == 0) {
        float bcc = 0.0f;
        for (int j = 0; j < CHN; j++) bcc += wp[o*CHN + j] * bo[j];
        d_bcomb[o] = bcc + bp[o];
    }
}

// ---------------------------------------------------------------------------
// QKV GEMM: q/k/v[m][j] = sum_k x[b][k][p] * W[j][k]
//   A tile from x (transposed layout, coalesced along p), 128x64x16 tiling
// ---------------------------------------------------------------------------
__global__ __launch_bounds__(256) void qkv_gemm(const float* __restrict__ x,
                                                const float* __restrict__ wq,
                                                const float* __restrict__ wk,
                                                const float* __restrict__ wv) {
    __shared__ float As[16][129];
    __shared__ float Bs[16][65];
    const float* W = (blockIdx.z == 0) ? wq : ((blockIdx.z == 1) ? wk : wv);
    float* C = (blockIdx.z == 0) ? d_q : ((blockIdx.z == 1) ? d_k : d_v);

    int m0 = blockIdx.x * 128, j0 = blockIdx.y * 64;
    int bb = m0 / NTOK, p0 = m0 % NTOK;
    const float* xb = x + (size_t)bb * CHN * NTOK + p0;
    int tid = threadIdx.x;
    int tx = tid & 15, ty = tid >> 4;   // col-fast mapping (coalesced C writes)

    float acc[8][4];
    #pragma unroll
    for (int i = 0; i < 8; i++)
        #pragma unroll
        for (int j = 0; j < 4; j++) acc[i][j] = 0.0f;

    for (int k0 = 0; k0 < CHN; k0 += 16) {
        #pragma unroll
        for (int i = 0; i < 8; i++) {
            int idx = tid + i*256; int kk = idx >> 7, mm = idx & 127;
            As[kk][mm] = xb[(size_t)(k0 + kk) * NTOK + mm];
        }
        #pragma unroll
        for (int i = 0; i < 4; i++) {
            int idx = tid + i*256; int kk = idx & 15, jj = idx >> 4;
            Bs[kk][jj] = W[(j0 + jj) * CHN + k0 + kk];
        }
        __syncthreads();
        #pragma unroll
        for (int kk = 0; kk < 16; kk++) {
            float a[8], bv[4];
            #pragma unroll
            for (int i = 0; i < 8; i++) a[i] = As[kk][ty + 16*i];
            #pragma unroll
            for (int j = 0; j < 4; j++) bv[j] = Bs[kk][tx + 16*j];
            #pragma unroll
            for (int i = 0; i < 8; i++)
                #pragma unroll
                for (int j = 0; j < 4; j++) acc[i][j] += a[i] * bv[j];
        }
        __syncthreads();
    }
    #pragma unroll
    for (int i = 0; i < 8; i++)
        #pragma unroll
        for (int j = 0; j < 4; j++)
            C[(size_t)(m0 + ty + 16*i) * CHN + (j0 + tx + 16*j)] = acc[i][j];
}

// ---------------------------------------------------------------------------
// k features pass 1: dash = dn * (k . proj_m); store (dash - diag); atomicMax
//   128 threads = features, 32 tokens per block
// ---------------------------------------------------------------------------
__global__ __launch_bounds__(128) void k_feat(const float* __restrict__ proj) {
    int bh = blockIdx.y, chunk = blockIdx.x;
    int b = bh / HEADS, hd = bh % HEADS;
    int p0 = chunk * 32;
    int t = threadIdx.x;

    __shared__ float k_s[32][33];
    __shared__ float diag_s[32];
    __shared__ float red_s[4];

    float pr[32];
    #pragma unroll
    for (int i = 0; i < 8; i++) {
        float4 f = ((const float4*)proj)[t*8 + i];
        pr[4*i+0] = f.x; pr[4*i+1] = f.y; pr[4*i+2] = f.z; pr[4*i+3] = f.w;
    }

    size_t base = ((size_t)(b * NTOK + p0)) * CHN + hd * DH;
    #pragma unroll
    for (int i = 0; i < 8; i++) {
        int idx = t + i*128; int tok = idx >> 5, d = idx & 31;
        k_s[tok][d] = d_k[base + (size_t)tok * CHN + d];
    }
    __syncthreads();
    if (t < 32) {
        float s = 0.0f;
        #pragma unroll
        for (int d = 0; d < 32; d++) s += k_s[t][d] * k_s[t][d];
        diag_s[t] = s * HALF_DN2;
    }
    __syncthreads();

    float lmax = -INFINITY;
    size_t orow = ((size_t)bh * NTOK + p0) * NB + t;
    for (int tok = 0; tok < 32; tok++) {
        float dash = 0.0f;
        #pragma unroll
        for (int d = 0; d < 32; d++) dash += k_s[tok][d] * pr[d];
        dash *= DN;
        lmax = fmaxf(lmax, dash);
        d_kdash[orow + (size_t)tok * NB] = dash - diag_s[tok];
    }
    #pragma unroll
    for (int off = 16; off > 0; off >>= 1)
        lmax = fmaxf(lmax, __shfl_xor_sync(0xffffffffu, lmax, off));
    int w = t >> 5;
    if ((t & 31) == 0) red_s[w] = lmax;
    __syncthreads();
    if (t == 0) {
        float m = fmaxf(fmaxf(red_s[0], red_s[1]), fmaxf(red_s[2], red_s[3]));
        atomicMaxFloat(&d_kmax[bh], m);
    }
}

// ---------------------------------------------------------------------------
// k pass 2: kp = ratio*(exp(stored - kmax)+eps); accumulate ksum and ctx=kp^T v
//   64 tokens per block, 256 threads
// ---------------------------------------------------------------------------
__global__ __launch_bounds__(256) void k_ctx() {
    int bh = blockIdx.y, chunk = blockIdx.x;
    int b = bh / HEADS, hd = bh % HEADS;
    int p0 = chunk * 64;
    int t = threadIdx.x;

    __shared__ float kp_s[64][128];
    __shared__ float v_s[64][32];

    float km = d_kmax[bh];
    int m = t & 127;
    float ksp = 0.0f;
    size_t drow = ((size_t)bh * NTOK + p0) * NB;
    #pragma unroll
    for (int i = 0; i < 32; i++) {
        int idx = t + i*256; int tok = idx >> 7;
        float val = RATIO * (expf(d_kdash[drow + (size_t)tok * NB + m] - km) + FEPS);
        kp_s[tok][m] = val;
        ksp += val;
    }
    atomicAdd(&d_ksum[bh*NB + m], ksp);

    size_t vbase = ((size_t)(b * NTOK + p0)) * CHN + hd * DH;
    #pragma unroll
    for (int i = 0; i < 8; i++) {
        int idx = t + i*256; int tok = idx >> 5, d = idx & 31;
        v_s[tok][d] = d_v[vbase + (size_t)tok * CHN + d];
    }
    __syncthreads();

    int dhalf = t >> 7;   // 0 or 1 -> d range [0,16) or [16,32)
    float4 a0 = {0,0,0,0}, a1 = {0,0,0,0}, a2 = {0,0,0,0}, a3 = {0,0,0,0};
    const float4* v4 = (const float4*)v_s;  // [64][8]
    for (int tok = 0; tok < 64; tok++) {
        float kv = kp_s[tok][m];
        float4 c0 = v4[tok*8 + dhalf*4 + 0];
        float4 c1 = v4[tok*8 + dhalf*4 + 1];
        float4 c2 = v4[tok*8 + dhalf*4 + 2];
        float4 c3 = v4[tok*8 + dhalf*4 + 3];
        a0.x += kv*c0.x; a0.y += kv*c0.y; a0.z += kv*c0.z; a0.w += kv*c0.w;
        a1.x += kv*c1.x; a1.y += kv*c1.y; a1.z += kv*c1.z; a1.w += kv*c1.w;
        a2.x += kv*c2.x; a2.y += kv*c2.y; a2.z += kv*c2.z; a2.w += kv*c2.w;
        a3.x += kv*c3.x; a3.y += kv*c3.y; a3.z += kv*c3.z; a3.w += kv*c3.w;
    }
    float* ctx = &d_ctx[((size_t)bh * NB + m) * DH + dhalf * 16];
    atomicAdd(&ctx[0],  a0.x); atomicAdd(&ctx[1],  a0.y);
    atomicAdd(&ctx[2],  a0.z); atomicAdd(&ctx[3],  a0.w);
    atomicAdd(&ctx[4],  a1.x); atomicAdd(&ctx[5],  a1.y);
    atomicAdd(&ctx[6],  a1.z); atomicAdd(&ctx[7],  a1.w);
    atomicAdd(&ctx[8],  a2.x); atomicAdd(&ctx[9],  a2.y);
    atomicAdd(&ctx[10], a2.z); atomicAdd(&ctx[11], a2.w);
    atomicAdd(&ctx[12], a3.x); atomicAdd(&ctx[13], a3.y);
    atomicAdd(&ctx[14], a3.z); atomicAdd(&ctx[15], a3.w);
}

// ---------------------------------------------------------------------------
// q features + attention output (fused): qp never materialized to GMEM.
//   128 threads = features, 32 tokens per block.
// ---------------------------------------------------------------------------
__global__ __launch_bounds__(128) void q_attn(const float* __restrict__ proj) {
    int bh = blockIdx.y, chunk = blockIdx.x;
    int b = bh / HEADS, hd = bh % HEADS;
    int p0 = chunk * 32;
    int t = threadIdx.x;

    __shared__ float q_s[32][33];
    __shared__ float diag_s[32];
    __shared__ float maxred[4], sumred[4];
    __shared__ float qp_s[32][129];
    __shared__ float ctx_s[NB*DH];
    __shared__ float ksum_s[NB];
    __shared__ float dinv_s[32];

    float pr[32];
    #pragma unroll
    for (int i = 0; i < 8; i++) {
        float4 f = ((const float4*)proj)[t*8 + i];
        pr[4*i+0] = f.x; pr[4*i+1] = f.y; pr[4*i+2] = f.z; pr[4*i+3] = f.w;
    }
    #pragma unroll
    for (int i = 0; i < 32; i++)
        ctx_s[t + i*128] = d_ctx[(size_t)bh * NB * DH + t + i*128];
    ksum_s[t] = d_ksum[bh*NB + t];

    size_t base = ((size_t)(b * NTOK + p0)) * CHN + hd * DH;
    #pragma unroll
    for (int i = 0; i < 8; i++) {
        int idx = t + i*128; int tok = idx >> 5, d = idx & 31;
        q_s[tok][d] = d_q[base + (size_t)tok * CHN + d];
    }
    __syncthreads();
    if (t < 32) {
        float s = 0.0f;
        #pragma unroll
        for (int d = 0; d < 32; d++) s += q_s[t][d] * q_s[t][d];
        diag_s[t] = s * HALF_DN2;
    }
    __syncthreads();

    int w = t >> 5, lane = t & 31;
    for (int tok = 0; tok < 32; tok++) {
        float dash = 0.0f;
        #pragma unroll
        for (int d = 0; d < 32; d++) dash += q_s[tok][d] * pr[d];
        dash *= DN;
        // block max over 128 features (raw dash, per reference)
        float v = dash;
        #pragma unroll
        for (int off = 16; off > 0; off >>= 1)
            v = fmaxf(v, __shfl_xor_sync(0xffffffffu, v, off));
        if (lane == 0) maxred[w] = v;
        __syncthreads();
        float mx = fmaxf(fmaxf(maxred[0], maxred[1]), fmaxf(maxred[2], maxred[3]));
        float qp = RATIO * (expf(dash - diag_s[tok] - mx) + FEPS);
        qp_s[tok][t] = qp;
        // denominator = qp . ksum
        float s = qp * ksum_s[t];
        #pragma unroll
        for (int off = 16; off > 0; off >>= 1)
            s += __shfl_xor_sync(0xffffffffu, s, off);
        if (lane == 0) sumred[w] = s;
        __syncthreads();
        if (t == 0)
            dinv_s[tok] = 1.0f / (sumred[0] + sumred[1] + sumred[2] + sumred[3]);
    }
    __syncthreads();

    // phase 2: out[tok][d] = dinv * sum_m qp[tok][m] * ctx[m][d]
    int tok = t >> 2, quad = t & 3;
    const float4* c4 = (const float4*)ctx_s;  // [128][8]
    float4 a0 = {0,0,0,0}, a1 = {0,0,0,0};
    const float* qprow = &qp_s[tok][0];
    #pragma unroll 4
    for (int m2 = 0; m2 < NB; m2++) {
        float qv = qprow[m2];
        float4 c0 = c4[m2*8 + quad*2 + 0];
        float4 c1 = c4[m2*8 + quad*2 + 1];
        a0.x += qv*c0.x; a0.y += qv*c0.y; a0.z += qv*c0.z; a0.w += qv*c0.w;
        a1.x += qv*c1.x; a1.y += qv*c1.y; a1.z += qv*c1.z; a1.w += qv*c1.w;
    }
    float di = dinv_s[tok];
    a0.x *= di; a0.y *= di; a0.z *= di; a0.w *= di;
    a1.x *= di; a1.y *= di; a1.z *= di; a1.w *= di;
    float4* outp = (float4*)&d_attn[((size_t)(b*NTOK + p0 + tok)) * CHN + hd*DH + quad*8];
    outp[0] = a0;
    outp[1] = a1;
}

// ---------------------------------------------------------------------------
// final GEMM: out[b][ch][p] = attn[m] . wcomb[ch] + bcomb[ch]
//   row-fast thread mapping -> coalesced transposed writes
// ---------------------------------------------------------------------------
__global__ __launch_bounds__(256) void out_gemm(float* __restrict__ out) {
    __shared__ float As[16][129];
    __shared__ float Bs[16][65];
    int m0 = blockIdx.x * 128, j0 = blockIdx.y * 64;
    int tid = threadIdx.x;
    int ty = tid & 15, tx = tid >> 4;   // row-fast

    float acc[8][4];
    #pragma unroll
    for (int i = 0; i < 8; i++)
        #pragma unroll
        for (int j = 0; j < 4; j++) acc[i][j] = 0.0f;

    for (int k0 = 0; k0 < CHN; k0 += 16) {
        #pragma unroll
        for (int i = 0; i < 8; i++) {
            int idx = tid + i*256; int mm = idx >> 4, kk = idx & 15;
            As[kk][mm] = d_attn[(size_t)(m0 + mm) * CHN + k0 + kk];
        }
        #pragma unroll
        for (int i = 0; i < 4; i++) {
            int idx = tid + i*256; int jj = idx >> 4, kk = idx & 15;
            Bs[kk][jj] = d_wcomb[(j0 + jj) * CHN + k0 + kk];
        }
        __syncthreads();
        #pragma unroll
        for (int kk = 0; kk < 16; kk++) {
            float a[8], bv[4];
            #pragma unroll
            for (int i = 0; i < 8; i++) a[i] = As[kk][ty + 16*i];
            #pragma unroll
            for (int j = 0; j < 4; j++) bv[j] = Bs[kk][tx + 16*j];
            #pragma unroll
            for (int i = 0; i < 8; i++)
                #pragma unroll
                for (int j = 0; j < 4; j++) acc[i][j] += a[i] * bv[j];
        }
        __syncthreads();
    }
    int b = m0 / NTOK, p0 = m0 % NTOK;
    #pragma unroll
    for (int j = 0; j < 4; j++) {
        int ch = j0 + tx + 16*j;
        float bias = d_bcomb[ch];
        #pragma unroll
        for (int i = 0; i < 8; i++) {
            int p = p0 + ty + 16*i;
            out[(size_t)(b*CHN + ch) * NTOK + p] = acc[i][j] + bias;
        }
    }
}

extern "C" void kernel_launch(void* const* d_in, const int* in_sizes, int n_in,
                              void* d_out, int out_size) {
    const float* x    = (const float*)d_in[0];
    const float* wq   = (const float*)d_in[1];
    const float* wk   = (const float*)d_in[2];
    const float* wv   = (const float*)d_in[3];
    const float* wo   = (const float*)d_in[4];
    const float* bo   = (const float*)d_in[5];
    const float* proj = (const float*)d_in[6];
    const float* wp   = (const float*)d_in[7];
    const float* bp   = (const float*)d_in[8];
    float* out = (float*)d_out;

    init_k<<<512, 256>>>();
    wcomb_k<<<256, 256>>>(wo, bo, wp, bp);
    qkv_gemm<<<dim3(288, 4, 3), 256>>>(x, wq, wk, wv);
    k_feat<<<dim3(288, BH), 128>>>(proj);
    k_ctx<<<dim3(144, BH), 256>>>();
    q_attn<<<dim3(288, BH), 128>>>(proj);
    out_gemm<<<dim3(288, 4), 256>>>(out);
}

// round 2
// speedup vs baseline: 1.4810x; 1.4810x over previous
#include <cuda_runtime.h>
#include <math.h>

#define NTOK 9216
#define BATCH 4
#define CHN 256
#define HEADS 8
#define DH 32
#define NB 128
#define BH (BATCH*HEADS)      // 32
#define MTOT (BATCH*NTOK)     // 36864

#define DN 0.4204482076268573f        // 32^-0.25
#define HALF_DN2 0.08838834764831845f // 0.5 * 32^-0.5
#define RATIO 0.08838834764831845f    // 128^-0.5
#define FEPS 1e-4f

static __device__ float d_q[MTOT*CHN];
static __device__ float d_k[MTOT*CHN];
static __device__ float d_v[MTOT*CHN];
static __device__ float d_attn[MTOT*CHN];
static __device__ float d_ctxe[BH*NB*DH];   // sum e*v (pre-scale)
static __device__ float d_ctx[BH*NB*DH];    // finalized
static __device__ float d_ksum1[BH*NB];     // sum e
static __device__ float d_ksum[BH*NB];      // finalized
static __device__ float d_vsum[BH*DH];      // sum v
static __device__ float d_kmax[BH];
static __device__ float d_wcomb[CHN*CHN];
static __device__ float d_bcomb[CHN];

// ---- f32x2 packed helpers -------------------------------------------------
__device__ __forceinline__ void ffma2(unsigned long long& d,
                                      unsigned long long a,
                                      unsigned long long b) {
    asm("fma.rn.f32x2 %0, %1, %2, %0;" : "+l"(d) : "l"(a), "l"(b));
}
__device__ __forceinline__ unsigned long long dupf(float a) {
    unsigned long long u;
    asm("mov.b64 %0, {%1, %1};" : "=l"(u) : "f"(a));
    return u;
}
__device__ __forceinline__ float2 ull2f2(unsigned long long u) {
    float2 f;
    asm("mov.b64 {%0, %1}, %2;" : "=f"(f.x), "=f"(f.y) : "l"(u));
    return f;
}

__device__ __forceinline__ void atomicMaxFloat(float* addr, float val) {
    int* ai = (int*)addr;
    int old = __float_as_int(*addr);
    while (__int_as_float(old) < val) {
        int assumed = old;
        old = atomicCAS(ai, assumed, __float_as_int(val));
        if (old == assumed) break;
    }
}

// ---------------------------------------------------------------------------
// init
// ---------------------------------------------------------------------------
__global__ void init_k() {
    int i = blockIdx.x * 256 + threadIdx.x;
    if (i < BH*NB*DH) d_ctxe[i] = 0.0f;
    if (i < BH*NB)    d_ksum1[i] = 0.0f;
    if (i < BH*DH)    d_vsum[i] = 0.0f;
    if (i < BH)       d_kmax[i] = -INFINITY;
}

// ---------------------------------------------------------------------------
// combined weight: wcomb = wp @ wo ; bcomb = wp @ bo + bp
// ---------------------------------------------------------------------------
__global__ __launch_bounds__(256) void wcomb_k(const float* __restrict__ wo,
                                               const float* __restrict__ bo,
                                               const float* __restrict__ wp,
                                               const float* __restrict__ bp) {
    int o = blockIdx.x;
    int c = threadIdx.x;
    float acc = 0.0f;
    for (int j = 0; j < CHN; j++) acc += wp[o*CHN + j] * wo[j*CHN + c];
    d_wcomb[o*CHN + c] = acc;
    if (c == 0) {
        float bcc = 0.0f;
        for (int j = 0; j < CHN; j++) bcc += wp[o*CHN + j] * bo[j];
        d_bcomb[o] = bcc + bp[o];
    }
}

// ---------------------------------------------------------------------------
// QKV GEMM via FFMA2: 128x128 tile, K-tile 8, double buffered.
// A = x (k-major along tokens), B = W (j-major, k contiguous -> transpose load)
// ---------------------------------------------------------------------------
__global__ __launch_bounds__(256, 2) void qkv_gemm(const float* __restrict__ x,
                                                   const float* __restrict__ wq,
                                                   const float* __restrict__ wk,
                                                   const float* __restrict__ wv) {
    __shared__ unsigned long long As2[2][8][130];  // duplicated A values
    __shared__ float Bs[2][8][132];

    const float* W = (blockIdx.z == 0) ? wq : ((blockIdx.z == 1) ? wk : wv);
    float* C = (blockIdx.z == 0) ? d_q : ((blockIdx.z == 1) ? d_k : d_v);

    int m0 = blockIdx.x * 128, j0 = blockIdx.y * 128;
    int bb = m0 / NTOK, p0 = m0 % NTOK;
    const float* xb = x + (size_t)bb * CHN * NTOK + p0;
    int tid = threadIdx.x;
    int aRow = tid >> 5, aCol = (tid & 31) * 4;
    int bRow = tid >> 1, bK = (tid & 1) * 4;
    int tx = tid & 15, ty = tid >> 4;

    unsigned long long acc[8][4];
    #pragma unroll
    for (int i = 0; i < 8; i++)
        #pragma unroll
        for (int j = 0; j < 4; j++) acc[i][j] = 0ull;

    float4 av = *(const float4*)&xb[(size_t)aRow * NTOK + aCol];
    float4 bv = *(const float4*)&W[(size_t)(j0 + bRow) * CHN + bK];
    {
        ulonglong2* pa = (ulonglong2*)&As2[0][aRow][aCol];
        pa[0] = make_ulonglong2(dupf(av.x), dupf(av.y));
        pa[1] = make_ulonglong2(dupf(av.z), dupf(av.w));
        Bs[0][bK+0][bRow] = bv.x; Bs[0][bK+1][bRow] = bv.y;
        Bs[0][bK+2][bRow] = bv.z; Bs[0][bK+3][bRow] = bv.w;
    }
    __syncthreads();

    for (int kt = 0; kt < CHN/8; kt++) {
        int buf = kt & 1;
        if (kt < CHN/8 - 1) {
            int k0 = (kt + 1) * 8;
            av = *(const float4*)&xb[(size_t)(k0 + aRow) * NTOK + aCol];
            bv = *(const float4*)&W[(size_t)(j0 + bRow) * CHN + k0 + bK];
        }
        #pragma unroll
        for (int kk = 0; kk < 8; kk++) {
            const unsigned long long* arow = &As2[buf][kk][0];
            ulonglong2 a01 = *(const ulonglong2*)&arow[ty*4];
            ulonglong2 a23 = *(const ulonglong2*)&arow[ty*4+2];
            ulonglong2 a45 = *(const ulonglong2*)&arow[ty*4+64];
            ulonglong2 a67 = *(const ulonglong2*)&arow[ty*4+66];
            const float* brow = &Bs[buf][kk][0];
            ulonglong2 bl = *(const ulonglong2*)&brow[tx*4];
            ulonglong2 bh = *(const ulonglong2*)&brow[tx*4+64];
            unsigned long long a_[8] = {a01.x,a01.y,a23.x,a23.y,a45.x,a45.y,a67.x,a67.y};
            unsigned long long b_[4] = {bl.x,bl.y,bh.x,bh.y};
            #pragma unroll
            for (int i = 0; i < 8; i++)
                #pragma unroll
                for (int j = 0; j < 4; j++) ffma2(acc[i][j], a_[i], b_[j]);
        }
        if (kt < CHN/8 - 1) {
            int nb = buf ^ 1;
            ulonglong2* pa = (ulonglong2*)&As2[nb][aRow][aCol];
            pa[0] = make_ulonglong2(dupf(av.x), dupf(av.y));
            pa[1] = make_ulonglong2(dupf(av.z), dupf(av.w));
            Bs[nb][bK+0][bRow] = bv.x; Bs[nb][bK+1][bRow] = bv.y;
            Bs[nb][bK+2][bRow] = bv.z; Bs[nb][bK+3][bRow] = bv.w;
            __syncthreads();
        }
    }
    #pragma unroll
    for (int i = 0; i < 8; i++) {
        int row = m0 + ty*4 + ((i < 4) ? i : (60 + i));
        float2 p0_ = ull2f2(acc[i][0]), p1_ = ull2f2(acc[i][1]);
        float2 p2_ = ull2f2(acc[i][2]), p3_ = ull2f2(acc[i][3]);
        *(float4*)&C[(size_t)row*CHN + j0 + tx*4]      = make_float4(p0_.x, p0_.y, p1_.x, p1_.y);
        *(float4*)&C[(size_t)row*CHN + j0 + tx*4 + 64] = make_float4(p2_.x, p2_.y, p3_.x, p3_.y);
    }
}

// ---------------------------------------------------------------------------
// fused k path: dash -> e=exp(dash-diag); accumulate sum e, sum e*v, sum v, max
// grid (32, BH); each block loops 9 tiles of 32 tokens; atomics only at end
// ---------------------------------------------------------------------------
__global__ __launch_bounds__(256) void k_fused(const float* __restrict__ proj) {
    int bh = blockIdx.y, chunk = blockIdx.x;
    int b = bh / HEADS, hd = bh % HEADS;
    int t = threadIdx.x;
    int m = t & 127, half = t >> 7;

    __shared__ float k_s[32][36];
    __shared__ float v_s[32][32];
    __shared__ float e_s[32][128];
    __shared__ float diag_s[32];
    __shared__ float red_s[8];

    unsigned long long pr2[16];
    {
        const float4* p4 = (const float4*)proj + m*8;
        #pragma unroll
        for (int i = 0; i < 8; i++) {
            float4 f = p4[i];
            pr2[2*i]   = make_ulonglong2(dupf(0.f),0).x; // placeholder overwritten below
            asm("mov.b64 %0, {%1, %2};" : "=l"(pr2[2*i])   : "f"(f.x), "f"(f.y));
            asm("mov.b64 %0, {%1, %2};" : "=l"(pr2[2*i+1]) : "f"(f.z), "f"(f.w));
        }
    }

    float lmax = -INFINITY;
    float ksloc = 0.0f;
    float vloc = 0.0f;
    int vd = t & 31, vtok0 = (t >> 5) * 4;
    unsigned long long ctxa[8];
    #pragma unroll
    for (int i = 0; i < 8; i++) ctxa[i] = 0ull;

    for (int tile = 0; tile < 9; tile++) {
        int p0 = chunk * 288 + tile * 32;
        size_t kbase = ((size_t)(b * NTOK + p0)) * CHN + hd * DH;
        #pragma unroll
        for (int i = 0; i < 4; i++) {
            int idx = t + i*256; int tok = idx >> 5, d = idx & 31;
            k_s[tok][d] = d_k[kbase + (size_t)tok * CHN + d];
            v_s[tok][d] = d_v[kbase + (size_t)tok * CHN + d];
        }
        __syncthreads();
        if (t < 32) {
            float s = 0.0f;
            #pragma unroll
            for (int d = 0; d < 32; d++) s += k_s[t][d] * k_s[t][d];
            diag_s[t] = s * HALF_DN2;
        }
        #pragma unroll
        for (int i = 0; i < 4; i++) vloc += v_s[vtok0 + i][vd];
        __syncthreads();

        #pragma unroll
        for (int tt = 0; tt < 16; tt++) {
            int tok = half * 16 + tt;
            unsigned long long d2 = 0ull;
            const ulonglong2* kr = (const ulonglong2*)&k_s[tok][0];
            #pragma unroll
            for (int q = 0; q < 8; q++) {
                ulonglong2 kq = kr[q];
                ffma2(d2, kq.x, pr2[2*q]);
                ffma2(d2, kq.y, pr2[2*q+1]);
            }
            float2 dd = ull2f2(d2);
            float dash = (dd.x + dd.y) * DN;
            lmax = fmaxf(lmax, dash);
            float e = __expf(dash - diag_s[tok]);
            e_s[tok][m] = e;
            ksloc += e;
        }
        __syncthreads();

        for (int tok = 0; tok < 32; tok++) {
            unsigned long long ev = dupf(e_s[tok][m]);
            const ulonglong2* vr = (const ulonglong2*)&v_s[tok][half*16];
            ulonglong2 v0 = vr[0], v1 = vr[1], v2 = vr[2], v3 = vr[3];
            ffma2(ctxa[0], ev, v0.x); ffma2(ctxa[1], ev, v0.y);
            ffma2(ctxa[2], ev, v1.x); ffma2(ctxa[3], ev, v1.y);
            ffma2(ctxa[4], ev, v2.x); ffma2(ctxa[5], ev, v2.y);
            ffma2(ctxa[6], ev, v3.x); ffma2(ctxa[7], ev, v3.y);
        }
        __syncthreads();
    }

    // reductions / atomics
    #pragma unroll
    for (int off = 16; off > 0; off >>= 1)
        lmax = fmaxf(lmax, __shfl_xor_sync(0xffffffffu, lmax, off));
    if ((t & 31) == 0) red_s[t >> 5] = lmax;
    __syncthreads();
    if (t == 0) {
        float mm = red_s[0];
        #pragma unroll
        for (int i = 1; i < 8; i++) mm = fmaxf(mm, red_s[i]);
        atomicMaxFloat(&d_kmax[bh], mm);
    }
    atomicAdd(&d_ksum1[bh*NB + m], ksloc);
    atomicAdd(&d_vsum[bh*DH + vd], vloc);
    float* ctxp = &d_ctxe[((size_t)bh * NB + m) * DH + half * 16];
    #pragma unroll
    for (int i = 0; i < 8; i++) {
        float2 c = ull2f2(ctxa[i]);
        atomicAdd(&ctxp[2*i],   c.x);
        atomicAdd(&ctxp[2*i+1], c.y);
    }
}

// ---------------------------------------------------------------------------
// finalize: apply exp(-max) and +eps terms
// ---------------------------------------------------------------------------
__global__ __launch_bounds__(128) void k_final() {
    int bh = blockIdx.x, t = threadIdx.x;  // t = feature
    float scale = __expf(-d_kmax[bh]);
    d_ksum[bh*NB + t] = RATIO * (scale * d_ksum1[bh*NB + t] + FEPS * (float)NTOK);
    size_t base = ((size_t)bh * NB + t) * DH;
    #pragma unroll
    for (int d = 0; d < DH; d++)
        d_ctx[base + d] = RATIO * (scale * d_ctxe[base + d] + FEPS * d_vsum[bh*DH + d]);
}

// ---------------------------------------------------------------------------
// q features + attention output (fused, 3-phase, minimal barriers)
// ---------------------------------------------------------------------------
__global__ __launch_bounds__(128) void q_attn(const float* __restrict__ proj) {
    int bh = blockIdx.y, chunk = blockIdx.x;
    int b = bh / HEADS, hd = bh % HEADS;
    int p0 = chunk * 32;
    int t = threadIdx.x;

    __shared__ float q_s[32][36];
    __shared__ float qp_s[32][129];
    __shared__ float ctx_s[NB*DH];
    __shared__ float ksum_s[NB];
    __shared__ float diag_s[32];
    __shared__ float dinv_s[32];

    unsigned long long pr2[16];
    {
        const float4* p4 = (const float4*)proj + t*8;
        #pragma unroll
        for (int i = 0; i < 8; i++) {
            float4 f = p4[i];
            asm("mov.b64 %0, {%1, %2};" : "=l"(pr2[2*i])   : "f"(f.x), "f"(f.y));
            asm("mov.b64 %0, {%1, %2};" : "=l"(pr2[2*i+1]) : "f"(f.z), "f"(f.w));
        }
    }
    #pragma unroll
    for (int i = 0; i < 32; i++)
        ctx_s[t + i*128] = d_ctx[(size_t)bh * NB * DH + t + i*128];
    ksum_s[t] = d_ksum[bh*NB + t];

    size_t base = ((size_t)(b * NTOK + p0)) * CHN + hd * DH;
    #pragma unroll
    for (int i = 0; i < 8; i++) {
        int idx = t + i*128; int tok = idx >> 5, d = idx & 31;
        q_s[tok][d] = d_q[base + (size_t)tok * CHN + d];
    }
    __syncthreads();

    if (t < 32) {
        float s = 0.0f;
        #pragma unroll
        for (int d = 0; d < 32; d++) s += q_s[t][d] * q_s[t][d];
        diag_s[t] = s * HALF_DN2;
    }
    // phase 1: dash for all (tok, m=t)
    #pragma unroll 4
    for (int tok = 0; tok < 32; tok++) {
        unsigned long long d2 = 0ull;
        const ulonglong2* qr = (const ulonglong2*)&q_s[tok][0];
        #pragma unroll
        for (int q = 0; q < 8; q++) {
            ulonglong2 qq = qr[q];
            ffma2(d2, qq.x, pr2[2*q]);
            ffma2(d2, qq.y, pr2[2*q+1]);
        }
        float2 dd = ull2f2(d2);
        qp_s[tok][t] = (dd.x + dd.y) * DN;
    }
    __syncthreads();

    // phase 2: per-token max over 128 features, qp, denominator
    {
        int tok = t >> 2, g = t & 3;
        int fb = g * 32;
        float mx = -INFINITY;
        #pragma unroll
        for (int j = 0; j < 32; j++) {
            int f = fb + ((j + g*8) & 31);
            mx = fmaxf(mx, qp_s[tok][f]);
        }
        mx = fmaxf(mx, __shfl_xor_sync(0xffffffffu, mx, 1));
        mx = fmaxf(mx, __shfl_xor_sync(0xffffffffu, mx, 2));
        float dg = diag_s[tok];
        float den = 0.0f;
        #pragma unroll
        for (int j = 0; j < 32; j++) {
            int f = fb + ((j + g*8) & 31);
            float qp = RATIO * (__expf(qp_s[tok][f] - dg - mx) + FEPS);
            qp_s[tok][f] = qp;
            den += qp * ksum_s[f];
        }
        den += __shfl_xor_sync(0xffffffffu, den, 1);
        den += __shfl_xor_sync(0xffffffffu, den, 2);
        if (g == 0) dinv_s[tok] = 1.0f / den;
    }
    __syncthreads();

    // phase 3: out[tok][d] = dinv * sum_m qp[tok][m] * ctx[m][d]
    {
        int tok = t >> 2, quad = t & 3;
        const unsigned long long* c2 = (const unsigned long long*)ctx_s;
        unsigned long long acc2[4] = {0ull, 0ull, 0ull, 0ull};
        const float* qprow = &qp_s[tok][0];
        #pragma unroll 4
        for (int f = 0; f < NB; f++) {
            unsigned long long qv = dupf(qprow[f]);
            ulonglong2 c01 = *(const ulonglong2*)&c2[f*16 + quad*4];
            ulonglong2 c23 = *(const ulonglong2*)&c2[f*16 + quad*4 + 2];
            ffma2(acc2[0], qv, c01.x); ffma2(acc2[1], qv, c01.y);
            ffma2(acc2[2], qv, c23.x); ffma2(acc2[3], qv, c23.y);
        }
        float di = dinv_s[tok];
        float2 r0 = ull2f2(acc2[0]), r1 = ull2f2(acc2[1]);
        float2 r2 = ull2f2(acc2[2]), r3 = ull2f2(acc2[3]);
        float4* outp = (float4*)&d_attn[((size_t)(b*NTOK + p0 + tok)) * CHN + hd*DH + quad*8];
        outp[0] = make_float4(r0.x*di, r0.y*di, r1.x*di, r1.y*di);
        outp[1] = make_float4(r2.x*di, r2.y*di, r3.x*di, r3.y*di);
    }
}

// ---------------------------------------------------------------------------
// final GEMM (transposed output): out[ch][p] = wcomb[ch][:] . attn[p][:] + bias
// M = ch (256), N = tokens (36864). Both operands transpose-loaded.
// ---------------------------------------------------------------------------
__global__ __launch_bounds__(256, 2) void out_gemm(float* __restrict__ out) {
    __shared__ unsigned long long As2[2][8][130];
    __shared__ float Bs[2][8][132];

    int m0 = blockIdx.x * 128, n0 = blockIdx.y * 128;
    int bb = n0 / NTOK, p0 = n0 % NTOK;
    int tid = threadIdx.x;
    int jj = tid >> 1, kp = (tid & 1) * 4;
    int tx = tid & 15, ty = tid >> 4;

    unsigned long long acc[8][4];
    #pragma unroll
    for (int i = 0; i < 8; i++)
        #pragma unroll
        for (int j = 0; j < 4; j++) acc[i][j] = 0ull;

    float4 av = *(const float4*)&d_wcomb[(size_t)(m0 + jj) * CHN + kp];
    float4 bv = *(const float4*)&d_attn[(size_t)(n0 + jj) * CHN + kp];
    {
        As2[0][kp+0][jj] = dupf(av.x); As2[0][kp+1][jj] = dupf(av.y);
        As2[0][kp+2][jj] = dupf(av.z); As2[0][kp+3][jj] = dupf(av.w);
        Bs[0][kp+0][jj] = bv.x; Bs[0][kp+1][jj] = bv.y;
        Bs[0][kp+2][jj] = bv.z; Bs[0][kp+3][jj] = bv.w;
    }
    __syncthreads();

    for (int kt = 0; kt < CHN/8; kt++) {
        int buf = kt & 1;
        if (kt < CHN/8 - 1) {
            int k0 = (kt + 1) * 8;
            av = *(const float4*)&d_wcomb[(size_t)(m0 + jj) * CHN + k0 + kp];
            bv = *(const float4*)&d_attn[(size_t)(n0 + jj) * CHN + k0 + kp];
        }
        #pragma unroll
        for (int kk = 0; kk < 8; kk++) {
            const unsigned long long* arow = &As2[buf][kk][0];
            ulonglong2 a01 = *(const ulonglong2*)&arow[ty*4];
            ulonglong2 a23 = *(const ulonglong2*)&arow[ty*4+2];
            ulonglong2 a45 = *(const ulonglong2*)&arow[ty*4+64];
            ulonglong2 a67 = *(const ulonglong2*)&arow[ty*4+66];
            const float* brow = &Bs[buf][kk][0];
            ulonglong2 bl = *(const ulonglong2*)&brow[tx*4];
            ulonglong2 bh = *(const ulonglong2*)&brow[tx*4+64];
            unsigned long long a_[8] = {a01.x,a01.y,a23.x,a23.y,a45.x,a45.y,a67.x,a67.y};
            unsigned long long b_[4] = {bl.x,bl.y,bh.x,bh.y};
            #pragma unroll
            for (int i = 0; i < 8; i++)
                #pragma unroll
                for (int j = 0; j < 4; j++) ffma2(acc[i][j], a_[i], b_[j]);
        }
        if (kt < CHN/8 - 1) {
            int nb = buf ^ 1;
            As2[nb][kp+0][jj] = dupf(av.x); As2[nb][kp+1][jj] = dupf(av.y);
            As2[nb][kp+2][jj] = dupf(av.z); As2[nb][kp+3][jj] = dupf(av.w);
            Bs[nb][kp+0][jj] = bv.x; Bs[nb][kp+1][jj] = bv.y;
            Bs[nb][kp+2][jj] = bv.z; Bs[nb][kp+3][jj] = bv.w;
            __syncthreads();
        }
    }
    #pragma unroll
    for (int i = 0; i < 8; i++) {
        int ch = m0 + ty*4 + ((i < 4) ? i : (60 + i));
        float bias = d_bcomb[ch];
        float2 p0_ = ull2f2(acc[i][0]), p1_ = ull2f2(acc[i][1]);
        float2 p2_ = ull2f2(acc[i][2]), p3_ = ull2f2(acc[i][3]);
        size_t rb = (size_t)(bb*CHN + ch) * NTOK + p0;
        *(float4*)&out[rb + tx*4]      = make_float4(p0_.x+bias, p0_.y+bias, p1_.x+bias, p1_.y+bias);
        *(float4*)&out[rb + tx*4 + 64] = make_float4(p2_.x+bias, p2_.y+bias, p3_.x+bias, p3_.y+bias);
    }
}

extern "C" void kernel_launch(void* const* d_in, const int* in_sizes, int n_in,
                              void* d_out, int out_size) {
    const float* x    = (const float*)d_in[0];
    const float* wq   = (const float*)d_in[1];
    const float* wk   = (const float*)d_in[2];
    const float* wv   = (const float*)d_in[3];
    const float* wo   = (const float*)d_in[4];
    const float* bo   = (const float*)d_in[5];
    const float* proj = (const float*)d_in[6];
    const float* wp   = (const float*)d_in[7];
    const float* bp   = (const float*)d_in[8];
    float* out = (float*)d_out;

    init_k<<<512, 256>>>();
    wcomb_k<<<256, 256>>>(wo, bo, wp, bp);
    qkv_gemm<<<dim3(288, 2, 3), 256>>>(x, wq, wk, wv);
    k_fused<<<dim3(32, BH), 256>>>(proj);
    k_final<<<BH, 128>>>();
    q_attn<<<dim3(288, BH), 128>>>(proj);
    out_gemm<<<dim3(2, 288), 256>>>(out);
}

// round 3
// speedup vs baseline: 1.6074x; 1.0853x over previous
#include <cuda_runtime.h>
#include <math.h>

#define NTOK 9216
#define BATCH 4
#define CHN 256
#define HEADS 8
#define DH 32
#define NB 128
#define BH (BATCH*HEADS)      // 32
#define MTOT (BATCH*NTOK)     // 36864

#define DN 0.4204482076268573f        // 32^-0.25
#define HALF_DN2 0.08838834764831845f // 0.5 * 32^-0.5
#define RATIO 0.08838834764831845f    // 128^-0.5
#define FEPS 1e-4f

static __device__ float d_q[MTOT*CHN];
static __device__ float d_k[MTOT*CHN];
static __device__ float d_v[MTOT*CHN];
static __device__ float d_attn[MTOT*CHN];
static __device__ float d_ctxe[BH*NB*DH];   // sum e*v (pre-scale)
static __device__ float d_ctx[BH*NB*DH];    // finalized
static __device__ float d_ksum1[BH*NB];     // sum e
static __device__ float d_ksum[BH*NB];      // finalized
static __device__ float d_vsum[BH*DH];      // sum v
static __device__ float d_kmax[BH];
static __device__ float d_wcomb[CHN*CHN];
static __device__ float d_bcomb[CHN];

// ---- f32x2 packed helpers -------------------------------------------------
__device__ __forceinline__ void ffma2(unsigned long long& d,
                                      unsigned long long a,
                                      unsigned long long b) {
    asm("fma.rn.f32x2 %0, %1, %2, %0;" : "+l"(d) : "l"(a), "l"(b));
}
__device__ __forceinline__ unsigned long long dupf(float a) {
    unsigned long long u;
    asm("mov.b64 %0, {%1, %1};" : "=l"(u) : "f"(a));
    return u;
}
__device__ __forceinline__ float2 ull2f2(unsigned long long u) {
    float2 f;
    asm("mov.b64 {%0, %1}, %2;" : "=f"(f.x), "=f"(f.y) : "l"(u));
    return f;
}
__device__ __forceinline__ unsigned long long packf2(float a, float b) {
    unsigned long long u;
    asm("mov.b64 %0, {%1, %2};" : "=l"(u) : "f"(a), "f"(b));
    return u;
}

__device__ __forceinline__ void atomicMaxFloat(float* addr, float val) {
    int* ai = (int*)addr;
    int old = __float_as_int(*addr);
    while (__int_as_float(old) < val) {
        int assumed = old;
        old = atomicCAS(ai, assumed, __float_as_int(val));
        if (old == assumed) break;
    }
}

// ---------------------------------------------------------------------------
// init
// ---------------------------------------------------------------------------
__global__ void init_k() {
    int i = blockIdx.x * 256 + threadIdx.x;
    if (i < BH*NB*DH) d_ctxe[i] = 0.0f;
    if (i < BH*NB)    d_ksum1[i] = 0.0f;
    if (i < BH*DH)    d_vsum[i] = 0.0f;
    if (i < BH)       d_kmax[i] = -INFINITY;
}

// ---------------------------------------------------------------------------
// combined weight: wcomb = wp @ wo ; bcomb = wp @ bo + bp
// ---------------------------------------------------------------------------
__global__ __launch_bounds__(256) void wcomb_k(const float* __restrict__ wo,
                                               const float* __restrict__ bo,
                                               const float* __restrict__ wp,
                                               const float* __restrict__ bp) {
    int o = blockIdx.x;
    int c = threadIdx.x;
    float acc = 0.0f;
    for (int j = 0; j < CHN; j++) acc += wp[o*CHN + j] * wo[j*CHN + c];
    d_wcomb[o*CHN + c] = acc;
    if (c == 0) {
        float bcc = 0.0f;
        for (int j = 0; j < CHN; j++) bcc += wp[o*CHN + j] * bo[j];
        d_bcomb[o] = bcc + bp[o];
    }
}

// ---------------------------------------------------------------------------
// QKV GEMM via FFMA2, pair-along-m accumulators (no smem duplication).
// 128x128 tile, K-tile 8, double buffered.
// ---------------------------------------------------------------------------
__global__ __launch_bounds__(256, 2) void qkv_gemm(const float* __restrict__ x,
                                                   const float* __restrict__ wq,
                                                   const float* __restrict__ wk,
                                                   const float* __restrict__ wv) {
    __shared__ float As[2][8][132];
    __shared__ float Bs[2][8][132];

    const float* W = (blockIdx.z == 0) ? wq : ((blockIdx.z == 1) ? wk : wv);
    float* C = (blockIdx.z == 0) ? d_q : ((blockIdx.z == 1) ? d_k : d_v);

    int m0 = blockIdx.x * 128, j0 = blockIdx.y * 128;
    int bb = m0 / NTOK, p0 = m0 % NTOK;
    const float* xb = x + (size_t)bb * CHN * NTOK + p0;
    int tid = threadIdx.x;
    int aRow = tid >> 5, aCol = (tid & 31) * 4;
    int bRow = tid >> 1, bK = (tid & 1) * 4;
    int tx = tid & 15, ty = tid >> 4;

    unsigned long long acc[4][8];
    #pragma unroll
    for (int p = 0; p < 4; p++)
        #pragma unroll
        for (int j = 0; j < 8; j++) acc[p][j] = 0ull;

    float4 av = *(const float4*)&xb[(size_t)aRow * NTOK + aCol];
    float4 bv = *(const float4*)&W[(size_t)(j0 + bRow) * CHN + bK];
    *(float4*)&As[0][aRow][aCol] = av;
    Bs[0][bK+0][bRow] = bv.x; Bs[0][bK+1][bRow] = bv.y;
    Bs[0][bK+2][bRow] = bv.z; Bs[0][bK+3][bRow] = bv.w;
    __syncthreads();

    for (int kt = 0; kt < CHN/8; kt++) {
        int buf = kt & 1;
        if (kt < CHN/8 - 1) {
            int k0 = (kt + 1) * 8;
            av = *(const float4*)&xb[(size_t)(k0 + aRow) * NTOK + aCol];
            bv = *(const float4*)&W[(size_t)(j0 + bRow) * CHN + k0 + bK];
        }
        #pragma unroll
        for (int kk = 0; kk < 8; kk++) {
            ulonglong2 aLo = *(const ulonglong2*)&As[buf][kk][ty*4];
            ulonglong2 aHi = *(const ulonglong2*)&As[buf][kk][ty*4 + 64];
            float4 bLo = *(const float4*)&Bs[buf][kk][tx*4];
            float4 bHi = *(const float4*)&Bs[buf][kk][tx*4 + 64];
            unsigned long long ap[4] = {aLo.x, aLo.y, aHi.x, aHi.y};
            unsigned long long bd[8] = {dupf(bLo.x), dupf(bLo.y), dupf(bLo.z), dupf(bLo.w),
                                        dupf(bHi.x), dupf(bHi.y), dupf(bHi.z), dupf(bHi.w)};
            #pragma unroll
            for (int p = 0; p < 4; p++)
                #pragma unroll
                for (int j = 0; j < 8; j++) ffma2(acc[p][j], ap[p], bd[j]);
        }
        if (kt < CHN/8 - 1) {
            int nb = buf ^ 1;
            *(float4*)&As[nb][aRow][aCol] = av;
            Bs[nb][bK+0][bRow] = bv.x; Bs[nb][bK+1][bRow] = bv.y;
            Bs[nb][bK+2][bRow] = bv.z; Bs[nb][bK+3][bRow] = bv.w;
            __syncthreads();
        }
    }
    #pragma unroll
    for (int p = 0; p < 4; p++) {
        float2 c[8];
        #pragma unroll
        for (int j = 0; j < 8; j++) c[j] = ull2f2(acc[p][j]);
        int r = m0 + ((p >= 2) ? 64 : 0) + ty*4 + (p & 1)*2;
        *(float4*)&C[(size_t)r*CHN + j0 + tx*4]          = make_float4(c[0].x, c[1].x, c[2].x, c[3].x);
        *(float4*)&C[(size_t)r*CHN + j0 + tx*4 + 64]     = make_float4(c[4].x, c[5].x, c[6].x, c[7].x);
        *(float4*)&C[(size_t)(r+1)*CHN + j0 + tx*4]      = make_float4(c[0].y, c[1].y, c[2].y, c[3].y);
        *(float4*)&C[(size_t)(r+1)*CHN + j0 + tx*4 + 64] = make_float4(c[4].y, c[5].y, c[6].y, c[7].y);
    }
}

// ---------------------------------------------------------------------------
// fused k path: thread = (feature m, dim-half). dash partial combined via
// shfl_xor(1). diag + vsum computed from prefetch registers. Double-buffered
// tiles, one barrier per tile, no e_s round-trip.
// ---------------------------------------------------------------------------
__global__ __launch_bounds__(256, 3) void k_fused(const float* __restrict__ proj) {
    int bh = blockIdx.y, chunk = blockIdx.x;
    int b = bh / HEADS, hd = bh % HEADS;
    int t = threadIdx.x;
    int m = t >> 1, half = t & 1;

    __shared__ float k_s[2][32][36];
    __shared__ float v_s[2][32][36];
    __shared__ float diag_s[2][32];
    __shared__ float red_s[8];

    unsigned long long pr2[8];
    {
        const float4* p4 = (const float4*)(proj + m*32 + half*16);
        #pragma unroll
        for (int i = 0; i < 4; i++) {
            float4 f = p4[i];
            pr2[2*i]   = packf2(f.x, f.y);
            pr2[2*i+1] = packf2(f.z, f.w);
        }
    }

    int ltok = t >> 3, lseg = t & 7;
    int p0 = chunk * 288;
    size_t base0 = ((size_t)(b * NTOK + p0)) * CHN + hd * DH;
    float4 kv4 = *(const float4*)&d_k[base0 + (size_t)ltok * CHN + lseg*4];
    float4 vv4 = *(const float4*)&d_v[base0 + (size_t)ltok * CHN + lseg*4];

    float vs0 = 0, vs1 = 0, vs2 = 0, vs3 = 0;
    *(float4*)&k_s[0][ltok][lseg*4] = kv4;
    *(float4*)&v_s[0][ltok][lseg*4] = vv4;
    vs0 += vv4.x; vs1 += vv4.y; vs2 += vv4.z; vs3 += vv4.w;
    {
        float sq = kv4.x*kv4.x + kv4.y*kv4.y + kv4.z*kv4.z + kv4.w*kv4.w;
        sq += __shfl_xor_sync(0xffffffffu, sq, 1);
        sq += __shfl_xor_sync(0xffffffffu, sq, 2);
        sq += __shfl_xor_sync(0xffffffffu, sq, 4);
        if (lseg == 0) diag_s[0][ltok] = sq * HALF_DN2;
    }
    __syncthreads();

    float lmax = -INFINITY, ksloc = 0.0f;
    unsigned long long ctxa[8];
    #pragma unroll
    for (int i = 0; i < 8; i++) ctxa[i] = 0ull;

    for (int tile = 0; tile < 9; tile++) {
        int buf = tile & 1;
        if (tile < 8) {
            size_t baseN = ((size_t)(b * NTOK + p0 + (tile+1)*32)) * CHN + hd * DH;
            kv4 = *(const float4*)&d_k[baseN + (size_t)ltok * CHN + lseg*4];
            vv4 = *(const float4*)&d_v[baseN + (size_t)ltok * CHN + lseg*4];
        }
        #pragma unroll 4
        for (int tok = 0; tok < 32; tok++) {
            const ulonglong2* kr = (const ulonglong2*)&k_s[buf][tok][half*16];
            ulonglong2 k0 = kr[0], k1 = kr[1];
            unsigned long long d2a = 0ull, d2b = 0ull;
            ffma2(d2a, k0.x, pr2[0]); ffma2(d2b, k0.y, pr2[1]);
            ffma2(d2a, k1.x, pr2[2]); ffma2(d2b, k1.y, pr2[3]);
            const ulonglong2* kr2 = kr + 2;
            ulonglong2 k2 = kr2[0], k3 = kr2[1];
            ffma2(d2a, k2.x, pr2[4]); ffma2(d2b, k2.y, pr2[5]);
            ffma2(d2a, k3.x, pr2[6]); ffma2(d2b, k3.y, pr2[7]);
            float2 fa = ull2f2(d2a), fb = ull2f2(d2b);
            float part = fa.x + fa.y + fb.x + fb.y;
            float dash = (part + __shfl_xor_sync(0xffffffffu, part, 1)) * DN;
            lmax = fmaxf(lmax, dash);
            float e = __expf(dash - diag_s[buf][tok]);
            ksloc += e;
            unsigned long long ev = dupf(e);
            const ulonglong2* vr = (const ulonglong2*)&v_s[buf][tok][half*16];
            ulonglong2 v0 = vr[0], v1 = vr[1], v2 = vr[2], v3 = vr[3];
            ffma2(ctxa[0], ev, v0.x); ffma2(ctxa[1], ev, v0.y);
            ffma2(ctxa[2], ev, v1.x); ffma2(ctxa[3], ev, v1.y);
            ffma2(ctxa[4], ev, v2.x); ffma2(ctxa[5], ev, v2.y);
            ffma2(ctxa[6], ev, v3.x); ffma2(ctxa[7], ev, v3.y);
        }
        if (tile < 8) {
            int nb = buf ^ 1;
            *(float4*)&k_s[nb][ltok][lseg*4] = kv4;
            *(float4*)&v_s[nb][ltok][lseg*4] = vv4;
            vs0 += vv4.x; vs1 += vv4.y; vs2 += vv4.z; vs3 += vv4.w;
            float sq = kv4.x*kv4.x + kv4.y*kv4.y + kv4.z*kv4.z + kv4.w*kv4.w;
            sq += __shfl_xor_sync(0xffffffffu, sq, 1);
            sq += __shfl_xor_sync(0xffffffffu, sq, 2);
            sq += __shfl_xor_sync(0xffffffffu, sq, 4);
            if (lseg == 0) diag_s[nb][ltok] = sq * HALF_DN2;
            __syncthreads();
        }
    }

    // reductions / atomics
    #pragma unroll
    for (int off = 16; off > 0; off >>= 1)
        lmax = fmaxf(lmax, __shfl_xor_sync(0xffffffffu, lmax, off));
    if ((t & 31) == 0) red_s[t >> 5] = lmax;
    __syncthreads();
    if (t == 0) {
        float mm = red_s[0];
        #pragma unroll
        for (int i = 1; i < 8; i++) mm = fmaxf(mm, red_s[i]);
        atomicMaxFloat(&d_kmax[bh], mm);
    }
    if (half == 0) atomicAdd(&d_ksum1[bh*NB + m], ksloc);
    atomicAdd(&d_vsum[bh*DH + lseg*4 + 0], vs0);
    atomicAdd(&d_vsum[bh*DH + lseg*4 + 1], vs1);
    atomicAdd(&d_vsum[bh*DH + lseg*4 + 2], vs2);
    atomicAdd(&d_vsum[bh*DH + lseg*4 + 3], vs3);
    float* ctxp = &d_ctxe[((size_t)bh * NB + m) * DH + half * 16];
    #pragma unroll
    for (int i = 0; i < 8; i++) {
        float2 c = ull2f2(ctxa[i]);
        atomicAdd(&ctxp[2*i],   c.x);
        atomicAdd(&ctxp[2*i+1], c.y);
    }
}

// ---------------------------------------------------------------------------
// finalize: apply exp(-max) and +eps terms
// ---------------------------------------------------------------------------
__global__ __launch_bounds__(128) void k_final() {
    int bh = blockIdx.x, t = threadIdx.x;  // t = feature
    float scale = __expf(-d_kmax[bh]);
    d_ksum[bh*NB + t] = RATIO * (scale * d_ksum1[bh*NB + t] + FEPS * (float)NTOK);
    size_t base = ((size_t)bh * NB + t) * DH;
    #pragma unroll
    for (int d = 0; d < DH; d++)
        d_ctx[base + d] = RATIO * (scale * d_ctxe[base + d] + FEPS * d_vsum[bh*DH + d]);
}

// ---------------------------------------------------------------------------
// q features + attention output (fused, 3-phase, minimal barriers)
// ---------------------------------------------------------------------------
__global__ __launch_bounds__(128) void q_attn(const float* __restrict__ proj) {
    int bh = blockIdx.y, chunk = blockIdx.x;
    int b = bh / HEADS, hd = bh % HEADS;
    int p0 = chunk * 32;
    int t = threadIdx.x;

    __shared__ float q_s[32][36];
    __shared__ float qp_s[32][129];
    __shared__ float ctx_s[NB*DH];
    __shared__ float ksum_s[NB];
    __shared__ float diag_s[32];
    __shared__ float dinv_s[32];

    unsigned long long pr2[16];
    {
        const float4* p4 = (const float4*)proj + t*8;
        #pragma unroll
        for (int i = 0; i < 8; i++) {
            float4 f = p4[i];
            pr2[2*i]   = packf2(f.x, f.y);
            pr2[2*i+1] = packf2(f.z, f.w);
        }
    }
    #pragma unroll
    for (int i = 0; i < 32; i++)
        ctx_s[t + i*128] = d_ctx[(size_t)bh * NB * DH + t + i*128];
    ksum_s[t] = d_ksum[bh*NB + t];

    size_t base = ((size_t)(b * NTOK + p0)) * CHN + hd * DH;
    #pragma unroll
    for (int i = 0; i < 8; i++) {
        int idx = t + i*128; int tok = idx >> 5, d = idx & 31;
        q_s[tok][d] = d_q[base + (size_t)tok * CHN + d];
    }
    __syncthreads();

    if (t < 32) {
        float s = 0.0f;
        #pragma unroll
        for (int d = 0; d < 32; d++) s += q_s[t][d] * q_s[t][d];
        diag_s[t] = s * HALF_DN2;
    }
    // phase 1: dash for all (tok, m=t)
    #pragma unroll 4
    for (int tok = 0; tok < 32; tok++) {
        unsigned long long d2 = 0ull;
        const ulonglong2* qr = (const ulonglong2*)&q_s[tok][0];
        #pragma unroll
        for (int q = 0; q < 8; q++) {
            ulonglong2 qq = qr[q];
            ffma2(d2, qq.x, pr2[2*q]);
            ffma2(d2, qq.y, pr2[2*q+1]);
        }
        float2 dd = ull2f2(d2);
        qp_s[tok][t] = (dd.x + dd.y) * DN;
    }
    __syncthreads();

    // phase 2: per-token max over 128 features, qp, denominator
    {
        int tok = t >> 2, g = t & 3;
        int fb = g * 32;
        float mx = -INFINITY;
        #pragma unroll
        for (int j = 0; j < 32; j++) {
            int f = fb + ((j + g*8) & 31);
            mx = fmaxf(mx, qp_s[tok][f]);
        }
        mx = fmaxf(mx, __shfl_xor_sync(0xffffffffu, mx, 1));
        mx = fmaxf(mx, __shfl_xor_sync(0xffffffffu, mx, 2));
        float dg = diag_s[tok];
        float den = 0.0f;
        #pragma unroll
        for (int j = 0; j < 32; j++) {
            int f = fb + ((j + g*8) & 31);
            float qp = RATIO * (__expf(qp_s[tok][f] - dg - mx) + FEPS);
            qp_s[tok][f] = qp;
            den += qp * ksum_s[f];
        }
        den += __shfl_xor_sync(0xffffffffu, den, 1);
        den += __shfl_xor_sync(0xffffffffu, den, 2);
        if (g == 0) dinv_s[tok] = 1.0f / den;
    }
    __syncthreads();

    // phase 3: out[tok][d] = dinv * sum_m qp[tok][m] * ctx[m][d]
    {
        int tok = t >> 2, quad = t & 3;
        const unsigned long long* c2 = (const unsigned long long*)ctx_s;
        unsigned long long acc2[4] = {0ull, 0ull, 0ull, 0ull};
        const float* qprow = &qp_s[tok][0];
        #pragma unroll 4
        for (int f = 0; f < NB; f++) {
            unsigned long long qv = dupf(qprow[f]);
            ulonglong2 c01 = *(const ulonglong2*)&c2[f*16 + quad*4];
            ulonglong2 c23 = *(const ulonglong2*)&c2[f*16 + quad*4 + 2];
            ffma2(acc2[0], qv, c01.x); ffma2(acc2[1], qv, c01.y);
            ffma2(acc2[2], qv, c23.x); ffma2(acc2[3], qv, c23.y);
        }
        float di = dinv_s[tok];
        float2 r0 = ull2f2(acc2[0]), r1 = ull2f2(acc2[1]);
        float2 r2 = ull2f2(acc2[2]), r3 = ull2f2(acc2[3]);
        float4* outp = (float4*)&d_attn[((size_t)(b*NTOK + p0 + tok)) * CHN + hd*DH + quad*8];
        outp[0] = make_float4(r0.x*di, r0.y*di, r1.x*di, r1.y*di);
        outp[1] = make_float4(r2.x*di, r2.y*di, r3.x*di, r3.y*di);
    }
}

// ---------------------------------------------------------------------------
// final GEMM (transposed output): out[ch][p] = wcomb[ch][:] . attn[p][:] + bias
// ---------------------------------------------------------------------------
__global__ __launch_bounds__(256, 2) void out_gemm(float* __restrict__ out) {
    __shared__ float As[2][8][132];
    __shared__ float Bs[2][8][132];

    int m0 = blockIdx.x * 128, n0 = blockIdx.y * 128;
    int bb = n0 / NTOK, p0 = n0 % NTOK;
    int tid = threadIdx.x;
    int jj = tid >> 1, kp = (tid & 1) * 4;
    int tx = tid & 15, ty = tid >> 4;

    unsigned long long acc[4][8];
    #pragma unroll
    for (int p = 0; p < 4; p++)
        #pragma unroll
        for (int j = 0; j < 8; j++) acc[p][j] = 0ull;

    float4 av = *(const float4*)&d_wcomb[(size_t)(m0 + jj) * CHN + kp];
    float4 bv = *(const float4*)&d_attn[(size_t)(n0 + jj) * CHN + kp];
    As[0][kp+0][jj] = av.x; As[0][kp+1][jj] = av.y;
    As[0][kp+2][jj] = av.z; As[0][kp+3][jj] = av.w;
    Bs[0][kp+0][jj] = bv.x; Bs[0][kp+1][jj] = bv.y;
    Bs[0][kp+2][jj] = bv.z; Bs[0][kp+3][jj] = bv.w;
    __syncthreads();

    for (int kt = 0; kt < CHN/8; kt++) {
        int buf = kt & 1;
        if (kt < CHN/8 - 1) {
            int k0 = (kt + 1) * 8;
            av = *(const float4*)&d_wcomb[(size_t)(m0 + jj) * CHN + k0 + kp];
            bv = *(const float4*)&d_attn[(size_t)(n0 + jj) * CHN + k0 + kp];
        }
        #pragma unroll
        for (int kk = 0; kk < 8; kk++) {
            ulonglong2 aLo = *(const ulonglong2*)&As[buf][kk][ty*4];
            ulonglong2 aHi = *(const ulonglong2*)&As[buf][kk][ty*4 + 64];
            float4 bLo = *(const float4*)&Bs[buf][kk][tx*4];
            float4 bHi = *(const float4*)&Bs[buf][kk][tx*4 + 64];
            unsigned long long ap[4] = {aLo.x, aLo.y, aHi.x, aHi.y};
            unsigned long long bd[8] = {dupf(bLo.x), dupf(bLo.y), dupf(bLo.z), dupf(bLo.w),
                                        dupf(bHi.x), dupf(bHi.y), dupf(bHi.z), dupf(bHi.w)};
            #pragma unroll
            for (int p = 0; p < 4; p++)
                #pragma unroll
                for (int j = 0; j < 8; j++) ffma2(acc[p][j], ap[p], bd[j]);
        }
        if (kt < CHN/8 - 1) {
            int nb = buf ^ 1;
            As[nb][kp+0][jj] = av.x; As[nb][kp+1][jj] = av.y;
            As[nb][kp+2][jj] = av.z; As[nb][kp+3][jj] = av.w;
            Bs[nb][kp+0][jj] = bv.x; Bs[nb][kp+1][jj] = bv.y;
            Bs[nb][kp+2][jj] = bv.z; Bs[nb][kp+3][jj] = bv.w;
            __syncthreads();
        }
    }
    #pragma unroll
    for (int p = 0; p < 4; p++) {
        float2 c[8];
        #pragma unroll
        for (int j = 0; j < 8; j++) c[j] = ull2f2(acc[p][j]);
        int ch = m0 + ((p >= 2) ? 64 : 0) + ty*4 + (p & 1)*2;
        float b0 = d_bcomb[ch], b1 = d_bcomb[ch+1];
        size_t r0 = (size_t)(bb*CHN + ch) * NTOK + p0;
        size_t r1 = (size_t)(bb*CHN + ch + 1) * NTOK + p0;
        *(float4*)&out[r0 + tx*4]      = make_float4(c[0].x+b0, c[1].x+b0, c[2].x+b0, c[3].x+b0);
        *(float4*)&out[r0 + tx*4 + 64] = make_float4(c[4].x+b0, c[5].x+b0, c[6].x+b0, c[7].x+b0);
        *(float4*)&out[r1 + tx*4]      = make_float4(c[0].y+b1, c[1].y+b1, c[2].y+b1, c[3].y+b1);
        *(float4*)&out[r1 + tx*4 + 64] = make_float4(c[4].y+b1, c[5].y+b1, c[6].y+b1, c[7].y+b1);
    }
}

extern "C" void kernel_launch(void* const* d_in, const int* in_sizes, int n_in,
                              void* d_out, int out_size) {
    const float* x    = (const float*)d_in[0];
    const float* wq   = (const float*)d_in[1];
    const float* wk   = (const float*)d_in[2];
    const float* wv   = (const float*)d_in[3];
    const float* wo   = (const float*)d_in[4];
    const float* bo   = (const float*)d_in[5];
    const float* proj = (const float*)d_in[6];
    const float* wp   = (const float*)d_in[7];
    const float* bp   = (const float*)d_in[8];
    float* out = (float*)d_out;

    init_k<<<512, 256>>>();
    wcomb_k<<<256, 256>>>(wo, bo, wp, bp);
    qkv_gemm<<<dim3(288, 2, 3), 256>>>(x, wq, wk, wv);
    k_fused<<<dim3(32, BH), 256>>>(proj);
    k_final<<<BH, 128>>>();
    q_attn<<<dim3(288, BH), 128>>>(proj);
    out_gemm<<<dim3(2, 288), 256>>>(out);
}

// round 5
// speedup vs baseline: 1.8289x; 1.1379x over previous
#include <cuda_runtime.h>
#include <cuda_bf16.h>
#include <math.h>
#include <cstdint>

#define NTOK 9216
#define BATCH 4
#define CHN 256
#define HEADS 8
#define DH 32
#define NB 128
#define BH (BATCH*HEADS)      // 32
#define MTOT (BATCH*NTOK)     // 36864

#define DN 0.4204482076268573f        // 32^-0.25
#define HALF_DN2 0.08838834764831845f // 0.5 * 32^-0.5
#define RATIO 0.08838834764831845f    // 128^-0.5
#define FEPS 1e-4f

static __device__ float d_q[MTOT*CHN];
static __device__ float d_k[MTOT*CHN];
static __device__ float d_v[MTOT*CHN];
static __device__ float d_ctxe[BH*NB*DH];
static __device__ float d_ctx[BH*NB*DH];
static __device__ float d_ksum1[BH*NB];
static __device__ float d_ksum[BH*NB];
static __device__ float d_vsum[BH*DH];
static __device__ float d_kmax[BH];
static __device__ float d_bcomb[CHN];

// bf16 split-precision operands
static __device__ __nv_bfloat16 d_xth[(size_t)MTOT*CHN];
static __device__ __nv_bfloat16 d_xtl[(size_t)MTOT*CHN];
static __device__ __nv_bfloat16 d_w3h[3*CHN*CHN];
static __device__ __nv_bfloat16 d_w3l[3*CHN*CHN];
static __device__ __nv_bfloat16 d_ath[(size_t)MTOT*CHN];
static __device__ __nv_bfloat16 d_atl[(size_t)MTOT*CHN];
static __device__ __nv_bfloat16 d_wch[CHN*CHN];
static __device__ __nv_bfloat16 d_wcl[CHN*CHN];

// ---- f32x2 packed helpers -------------------------------------------------
__device__ __forceinline__ void ffma2(unsigned long long& d,
                                      unsigned long long a,
                                      unsigned long long b) {
    asm("fma.rn.f32x2 %0, %1, %2, %0;" : "+l"(d) : "l"(a), "l"(b));
}
__device__ __forceinline__ unsigned long long dupf(float a) {
    unsigned long long u;
    asm("mov.b64 %0, {%1, %1};" : "=l"(u) : "f"(a));
    return u;
}
__device__ __forceinline__ float2 ull2f2(unsigned long long u) {
    float2 f;
    asm("mov.b64 {%0, %1}, %2;" : "=f"(f.x), "=f"(f.y) : "l"(u));
    return f;
}
__device__ __forceinline__ unsigned long long packf2(float a, float b) {
    unsigned long long u;
    asm("mov.b64 %0, {%1, %2};" : "=l"(u) : "f"(a), "f"(b));
    return u;
}

// ---- mma.sync helpers -----------------------------------------------------
__device__ __forceinline__ uint32_t smem_u32(const void* p) {
    uint32_t a;
    asm("{ .reg .u64 t; cvta.to.shared.u64 t, %1; cvt.u32.u64 %0, t; }" : "=r"(a) : "l"(p));
    return a;
}
__device__ __forceinline__ void ldsm_x4(uint32_t* r, uint32_t addr) {
    asm volatile("ldmatrix.sync.aligned.m8n8.x4.shared.b16 {%0,%1,%2,%3}, [%4];"
        : "=r"(r[0]), "=r"(r[1]), "=r"(r[2]), "=r"(r[3]) : "r"(addr));
}
__device__ __forceinline__ void mma16816(float* c, const uint32_t* a, const uint32_t* b) {
    asm volatile("mma.sync.aligned.m16n8k16.row.col.f32.bf16.bf16.f32 "
        "{%0,%1,%2,%3}, {%4,%5,%6,%7}, {%8,%9}, {%0,%1,%2,%3};"
        : "+f"(c[0]), "+f"(c[1]), "+f"(c[2]), "+f"(c[3])
        : "r"(a[0]), "r"(a[1]), "r"(a[2]), "r"(a[3]), "r"(b[0]), "r"(b[1]));
}

__device__ __forceinline__ void atomicMaxFloat(float* addr, float val) {
    int* ai = (int*)addr;
    int old = __float_as_int(*addr);
    while (__int_as_float(old) < val) {
        int assumed = old;
        old = atomicCAS(ai, assumed, __float_as_int(val));
        if (old == assumed) break;
    }
}

__device__ __forceinline__ void split_bf16(float v, __nv_bfloat16& h, __nv_bfloat16& l) {
    h = __float2bfloat16_rn(v);
    l = __float2bfloat16_rn(v - __bfloat162float(h));
}

// ---------------------------------------------------------------------------
// init
// ---------------------------------------------------------------------------
__global__ void init_k() {
    int i = blockIdx.x * 256 + threadIdx.x;
    if (i < BH*NB*DH) d_ctxe[i] = 0.0f;
    if (i < BH*NB)    d_ksum1[i] = 0.0f;
    if (i < BH*DH)    d_vsum[i] = 0.0f;
    if (i < BH)       d_kmax[i] = -INFINITY;
}

// ---------------------------------------------------------------------------
// weight conversions
// ---------------------------------------------------------------------------
__global__ __launch_bounds__(256) void conv_w(const float* __restrict__ wq,
                                              const float* __restrict__ wk,
                                              const float* __restrict__ wv) {
    int z = blockIdx.y, o = blockIdx.x, c = threadIdx.x;
    const float* W = (z == 0) ? wq : ((z == 1) ? wk : wv);
    float v = W[o*CHN + c];
    __nv_bfloat16 h, l; split_bf16(v, h, l);
    d_w3h[(z*CHN + o)*CHN + c] = h;
    d_w3l[(z*CHN + o)*CHN + c] = l;
}

__global__ __launch_bounds__(256) void wcomb_k(const float* __restrict__ wo,
                                               const float* __restrict__ bo,
                                               const float* __restrict__ wp,
                                               const float* __restrict__ bp) {
    int o = blockIdx.x, c = threadIdx.x;
    float acc = 0.0f;
    for (int j = 0; j < CHN; j++) acc += wp[o*CHN + j] * wo[j*CHN + c];
    __nv_bfloat16 h, l; split_bf16(acc, h, l);
    d_wch[o*CHN + c] = h;
    d_wcl[o*CHN + c] = l;
    if (c == 0) {
        float bcc = 0.0f;
        for (int j = 0; j < CHN; j++) bcc += wp[o*CHN + j] * bo[j];
        d_bcomb[o] = bcc + bp[o];
    }
}

// ---------------------------------------------------------------------------
// transpose x -> xt bf16 hi/lo : xt[(b*NTOK+p)][c]
// ---------------------------------------------------------------------------
__global__ __launch_bounds__(256) void xt_k(const float* __restrict__ x) {
    __shared__ float t[32][33];
    int b = blockIdx.z, c0 = blockIdx.y * 32, p0 = blockIdx.x * 32;
    int tx = threadIdx.x & 31, ty = threadIdx.x >> 5;
    #pragma unroll
    for (int i = 0; i < 4; i++) {
        int c = c0 + ty + i*8;
        t[ty + i*8][tx] = x[((size_t)(b*CHN + c))*NTOK + p0 + tx];
    }
    __syncthreads();
    #pragma unroll
    for (int i = 0; i < 4; i++) {
        int p = p0 + ty + i*8;
        float v = t[tx][ty + i*8];
        size_t gi = (size_t)(b*NTOK + p)*CHN + c0 + tx;
        __nv_bfloat16 h, l; split_bf16(v, h, l);
        d_xth[gi] = h;
        d_xtl[gi] = l;
    }
}

// ---------------------------------------------------------------------------
// QKV GEMM via mma.sync bf16 split precision. Block tile 128x64, 8 warps@32x32.
// ---------------------------------------------------------------------------
__global__ __launch_bounds__(256) void qkv_mms() {
    __shared__ __align__(16) __nv_bfloat16 Ah[128][40];
    __shared__ __align__(16) __nv_bfloat16 Al[128][40];
    __shared__ __align__(16) __nv_bfloat16 Bh[64][40];
    __shared__ __align__(16) __nv_bfloat16 Bl[64][40];

    int z = blockIdx.z;
    const __nv_bfloat16* WH = d_w3h + (size_t)z*CHN*CHN;
    const __nv_bfloat16* WL = d_w3l + (size_t)z*CHN*CHN;
    float* C = (z == 0) ? d_q : ((z == 1) ? d_k : d_v);
    int m0 = blockIdx.x * 128, n0 = blockIdx.y * 64;
    int tid = threadIdx.x, wid = tid >> 5, lane = tid & 31;
    int wm = (wid & 3) * 32, wn = (wid >> 2) * 32;

    float acc[2][4][4];
    #pragma unroll
    for (int mi = 0; mi < 2; mi++)
        #pragma unroll
        for (int ni = 0; ni < 4; ni++)
            #pragma unroll
            for (int q = 0; q < 4; q++) acc[mi][ni][q] = 0.0f;

    int arow = wm + (lane & 15);
    int acol8 = (lane >> 4) * 8;
    int brow = wn + ((lane >> 4) << 3) + (lane & 7);
    int bcol8 = ((lane >> 3) & 1) * 8;

    for (int ck = 0; ck < 8; ck++) {
        int k0 = ck * 32;
        #pragma unroll
        for (int j = 0; j < 2; j++) {
            int i = tid + j*256, row = i >> 2, cg = i & 3;
            size_t g = (size_t)(m0 + row)*CHN + k0 + cg*8;
            *(uint4*)&Ah[row][cg*8] = *(const uint4*)(d_xth + g);
            *(uint4*)&Al[row][cg*8] = *(const uint4*)(d_xtl + g);
        }
        {
            int row = tid >> 2, cg = tid & 3;
            size_t g = (size_t)(n0 + row)*CHN + k0 + cg*8;
            *(uint4*)&Bh[row][cg*8] = *(const uint4*)(WH + g);
            *(uint4*)&Bl[row][cg*8] = *(const uint4*)(WL + g);
        }
        __syncthreads();
        #pragma unroll
        for (int ks = 0; ks < 32; ks += 16) {
            uint32_t ah[2][4], al[2][4], bh[2][4], bl[2][4];
            #pragma unroll
            for (int mi = 0; mi < 2; mi++) {
                ldsm_x4(ah[mi], smem_u32(&Ah[arow + mi*16][ks + acol8]));
                ldsm_x4(al[mi], smem_u32(&Al[arow + mi*16][ks + acol8]));
            }
            #pragma unroll
            for (int p = 0; p < 2; p++) {
                ldsm_x4(bh[p], smem_u32(&Bh[brow + p*16][ks + bcol8]));
                ldsm_x4(bl[p], smem_u32(&Bl[brow + p*16][ks + bcol8]));
            }
            #pragma unroll
            for (int mi = 0; mi < 2; mi++)
                #pragma unroll
                for (int ni = 0; ni < 4; ni++) {
                    const uint32_t* bhp = &bh[ni >> 1][(ni & 1)*2];
                    const uint32_t* blp = &bl[ni >> 1][(ni & 1)*2];
                    mma16816(acc[mi][ni], ah[mi], bhp);
                    mma16816(acc[mi][ni], ah[mi], blp);
                    mma16816(acc[mi][ni], al[mi], bhp);
                }
        }
        __syncthreads();
    }
    #pragma unroll
    for (int mi = 0; mi < 2; mi++)
        #pragma unroll
        for (int ni = 0; ni < 4; ni++) {
            int m = m0 + wm + mi*16 + (lane >> 2);
            int n = n0 + wn + ni*8 + 2*(lane & 3);
            *(float2*)&C[(size_t)m*CHN + n]     = make_float2(acc[mi][ni][0], acc[mi][ni][1]);
            *(float2*)&C[(size_t)(m+8)*CHN + n] = make_float2(acc[mi][ni][2], acc[mi][ni][3]);
        }
}

// ---------------------------------------------------------------------------
// fused k path (round-3 version)
// ---------------------------------------------------------------------------
__global__ __launch_bounds__(256, 3) void k_fused(const float* __restrict__ proj) {
    int bh = blockIdx.y, chunk = blockIdx.x;
    int b = bh / HEADS, hd = bh % HEADS;
    int t = threadIdx.x;
    int m = t >> 1, half = t & 1;

    __shared__ float k_s[2][32][36];
    __shared__ float v_s[2][32][36];
    __shared__ float diag_s[2][32];
    __shared__ float red_s[8];

    unsigned long long pr2[8];
    {
        const float4* p4 = (const float4*)(proj + m*32 + half*16);
        #pragma unroll
        for (int i = 0; i < 4; i++) {
            float4 f = p4[i];
            pr2[2*i]   = packf2(f.x, f.y);
            pr2[2*i+1] = packf2(f.z, f.w);
        }
    }

    int ltok = t >> 3, lseg = t & 7;
    int p0 = chunk * 288;
    size_t base0 = ((size_t)(b * NTOK + p0)) * CHN + hd * DH;
    float4 kv4 = *(const float4*)&d_k[base0 + (size_t)ltok * CHN + lseg*4];
    float4 vv4 = *(const float4*)&d_v[base0 + (size_t)ltok * CHN + lseg*4];

    float vs0 = 0, vs1 = 0, vs2 = 0, vs3 = 0;
    *(float4*)&k_s[0][ltok][lseg*4] = kv4;
    *(float4*)&v_s[0][ltok][lseg*4] = vv4;
    vs0 += vv4.x; vs1 += vv4.y; vs2 += vv4.z; vs3 += vv4.w;
    {
        float sq = kv4.x*kv4.x + kv4.y*kv4.y + kv4.z*kv4.z + kv4.w*kv4.w;
        sq += __shfl_xor_sync(0xffffffffu, sq, 1);
        sq += __shfl_xor_sync(0xffffffffu, sq, 2);
        sq += __shfl_xor_sync(0xffffffffu, sq, 4);
        if (lseg == 0) diag_s[0][ltok] = sq * HALF_DN2;
    }
    __syncthreads();

    float lmax = -INFINITY, ksloc = 0.0f;
    unsigned long long ctxa[8];
    #pragma unroll
    for (int i = 0; i < 8; i++) ctxa[i] = 0ull;

    for (int tile = 0; tile < 9; tile++) {
        int buf = tile & 1;
        if (tile < 8) {
            size_t baseN = ((size_t)(b * NTOK + p0 + (tile+1)*32)) * CHN + hd * DH;
            kv4 = *(const float4*)&d_k[baseN + (size_t)ltok * CHN + lseg*4];
            vv4 = *(const float4*)&d_v[baseN + (size_t)ltok * CHN + lseg*4];
        }
        #pragma unroll 4
        for (int tok = 0; tok < 32; tok++) {
            const ulonglong2* kr = (const ulonglong2*)&k_s[buf][tok][half*16];
            ulonglong2 k0 = kr[0], k1 = kr[1];
            unsigned long long d2a = 0ull, d2b = 0ull;
            ffma2(d2a, k0.x, pr2[0]); ffma2(d2b, k0.y, pr2[1]);
            ffma2(d2a, k1.x, pr2[2]); ffma2(d2b, k1.y, pr2[3]);
            const ulonglong2* kr2 = kr + 2;
            ulonglong2 k2 = kr2[0], k3 = kr2[1];
            ffma2(d2a, k2.x, pr2[4]); ffma2(d2b, k2.y, pr2[5]);
            ffma2(d2a, k3.x, pr2[6]); ffma2(d2b, k3.y, pr2[7]);
            float2 fa = ull2f2(d2a), fb = ull2f2(d2b);
            float part = fa.x + fa.y + fb.x + fb.y;
            float dash = (part + __shfl_xor_sync(0xffffffffu, part, 1)) * DN;
            lmax = fmaxf(lmax, dash);
            float e = __expf(dash - diag_s[buf][tok]);
            ksloc += e;
            unsigned long long ev = dupf(e);
            const ulonglong2* vr = (const ulonglong2*)&v_s[buf][tok][half*16];
            ulonglong2 v0 = vr[0], v1 = vr[1], v2 = vr[2], v3 = vr[3];
            ffma2(ctxa[0], ev, v0.x); ffma2(ctxa[1], ev, v0.y);
            ffma2(ctxa[2], ev, v1.x); ffma2(ctxa[3], ev, v1.y);
            ffma2(ctxa[4], ev, v2.x); ffma2(ctxa[5], ev, v2.y);
            ffma2(ctxa[6], ev, v3.x); ffma2(ctxa[7], ev, v3.y);
        }
        if (tile < 8) {
            int nb = buf ^ 1;
            *(float4*)&k_s[nb][ltok][lseg*4] = kv4;
            *(float4*)&v_s[nb][ltok][lseg*4] = vv4;
            vs0 += vv4.x; vs1 += vv4.y; vs2 += vv4.z; vs3 += vv4.w;
            float sq = kv4.x*kv4.x + kv4.y*kv4.y + kv4.z*kv4.z + kv4.w*kv4.w;
            sq += __shfl_xor_sync(0xffffffffu, sq, 1);
            sq += __shfl_xor_sync(0xffffffffu, sq, 2);
            sq += __shfl_xor_sync(0xffffffffu, sq, 4);
            if (lseg == 0) diag_s[nb][ltok] = sq * HALF_DN2;
            __syncthreads();
        }
    }

    #pragma unroll
    for (int off = 16; off > 0; off >>= 1)
        lmax = fmaxf(lmax, __shfl_xor_sync(0xffffffffu, lmax, off));
    if ((t & 31) == 0) red_s[t >> 5] = lmax;
    __syncthreads();
    if (t == 0) {
        float mm = red_s[0];
        #pragma unroll
        for (int i = 1; i < 8; i++) mm = fmaxf(mm, red_s[i]);
        atomicMaxFloat(&d_kmax[bh], mm);
    }
    if (half == 0) atomicAdd(&d_ksum1[bh*NB + m], ksloc);
    atomicAdd(&d_vsum[bh*DH + lseg*4 + 0], vs0);
    atomicAdd(&d_vsum[bh*DH + lseg*4 + 1], vs1);
    atomicAdd(&d_vsum[bh*DH + lseg*4 + 2], vs2);
    atomicAdd(&d_vsum[bh*DH + lseg*4 + 3], vs3);
    float* ctxp = &d_ctxe[((size_t)bh * NB + m) * DH + half * 16];
    #pragma unroll
    for (int i = 0; i < 8; i++) {
        float2 c = ull2f2(ctxa[i]);
        atomicAdd(&ctxp[2*i],   c.x);
        atomicAdd(&ctxp[2*i+1], c.y);
    }
}

// ---------------------------------------------------------------------------
// finalize
// ---------------------------------------------------------------------------
__global__ __launch_bounds__(128) void k_final() {
    int bh = blockIdx.x, t = threadIdx.x;
    float scale = __expf(-d_kmax[bh]);
    d_ksum[bh*NB + t] = RATIO * (scale * d_ksum1[bh*NB + t] + FEPS * (float)NTOK);
    size_t base = ((size_t)bh * NB + t) * DH;
    #pragma unroll
    for (int d = 0; d < DH; d++)
        d_ctx[base + d] = RATIO * (scale * d_ctxe[base + d] + FEPS * d_vsum[bh*DH + d]);
}

// ---------------------------------------------------------------------------
// q features + attention output: emits attn as bf16 hi/lo
// ---------------------------------------------------------------------------
__global__ __launch_bounds__(128) void q_attn(const float* __restrict__ proj) {
    int bh = blockIdx.y, chunk = blockIdx.x;
    int b = bh / HEADS, hd = bh % HEADS;
    int p0 = chunk * 32;
    int t = threadIdx.x;

    __shared__ float q_s[32][36];
    __shared__ float qp_s[32][129];
    __shared__ float ctx_s[NB*DH];
    __shared__ float ksum_s[NB];
    __shared__ float diag_s[32];
    __shared__ float dinv_s[32];

    unsigned long long pr2[16];
    {
        const float4* p4 = (const float4*)proj + t*8;
        #pragma unroll
        for (int i = 0; i < 8; i++) {
            float4 f = p4[i];
            pr2[2*i]   = packf2(f.x, f.y);
            pr2[2*i+1] = packf2(f.z, f.w);
        }
    }
    #pragma unroll
    for (int i = 0; i < 32; i++)
        ctx_s[t + i*128] = d_ctx[(size_t)bh * NB * DH + t + i*128];
    ksum_s[t] = d_ksum[bh*NB + t];

    size_t base = ((size_t)(b * NTOK + p0)) * CHN + hd * DH;
    #pragma unroll
    for (int i = 0; i < 8; i++) {
        int idx = t + i*128; int tok = idx >> 5, d = idx & 31;
        q_s[tok][d] = d_q[base + (size_t)tok * CHN + d];
    }
    __syncthreads();

    if (t < 32) {
        float s = 0.0f;
        #pragma unroll
        for (int d = 0; d < 32; d++) s += q_s[t][d] * q_s[t][d];
        diag_s[t] = s * HALF_DN2;
    }
    #pragma unroll 4
    for (int tok = 0; tok < 32; tok++) {
        unsigned long long d2 = 0ull;
        const ulonglong2* qr = (const ulonglong2*)&q_s[tok][0];
        #pragma unroll
        for (int q = 0; q < 8; q++) {
            ulonglong2 qq = qr[q];
            ffma2(d2, qq.x, pr2[2*q]);
            ffma2(d2, qq.y, pr2[2*q+1]);
        }
        float2 dd = ull2f2(d2);
        qp_s[tok][t] = (dd.x + dd.y) * DN;
    }
    __syncthreads();

    {
        int tok = t >> 2, g = t & 3;
        int fb = g * 32;
        float mx = -INFINITY;
        #pragma unroll
        for (int j = 0; j < 32; j++) {
            int f = fb + ((j + g*8) & 31);
            mx = fmaxf(mx, qp_s[tok][f]);
        }
        mx = fmaxf(mx, __shfl_xor_sync(0xffffffffu, mx, 1));
        mx = fmaxf(mx, __shfl_xor_sync(0xffffffffu, mx, 2));
        float dg = diag_s[tok];
        float den = 0.0f;
        #pragma unroll
        for (int j = 0; j < 32; j++) {
            int f = fb + ((j + g*8) & 31);
            float qp = RATIO * (__expf(qp_s[tok][f] - dg - mx) + FEPS);
            qp_s[tok][f] = qp;
            den += qp * ksum_s[f];
        }
        den += __shfl_xor_sync(0xffffffffu, den, 1);
        den += __shfl_xor_sync(0xffffffffu, den, 2);
        if (g == 0) dinv_s[tok] = 1.0f / den;
    }
    __syncthreads();

    {
        int tok = t >> 2, quad = t & 3;
        const unsigned long long* c2 = (const unsigned long long*)ctx_s;
        unsigned long long acc2[4] = {0ull, 0ull, 0ull, 0ull};
        const float* qprow = &qp_s[tok][0];
        #pragma unroll 4
        for (int f = 0; f < NB; f++) {
            unsigned long long qv = dupf(qprow[f]);
            ulonglong2 c01 = *(const ulonglong2*)&c2[f*16 + quad*4];
            ulonglong2 c23 = *(const ulonglong2*)&c2[f*16 + quad*4 + 2];
            ffma2(acc2[0], qv, c01.x); ffma2(acc2[1], qv, c01.y);
            ffma2(acc2[2], qv, c23.x); ffma2(acc2[3], qv, c23.y);
        }
        float di = dinv_s[tok];
        float2 r0 = ull2f2(acc2[0]), r1 = ull2f2(acc2[1]);
        float2 r2 = ull2f2(acc2[2]), r3 = ull2f2(acc2[3]);
        float vals[8] = {r0.x*di, r0.y*di, r1.x*di, r1.y*di,
                         r2.x*di, r2.y*di, r3.x*di, r3.y*di};
        unsigned short hs[8], ls[8];
        #pragma unroll
        for (int j = 0; j < 8; j++) {
            __nv_bfloat16 h, l; split_bf16(vals[j], h, l);
            hs[j] = *(unsigned short*)&h;
            ls[j] = *(unsigned short*)&l;
        }
        size_t gi = (size_t)(b*NTOK + p0 + tok)*CHN + hd*DH + quad*8;
        *(uint4*)&d_ath[gi] = *(uint4*)hs;
        *(uint4*)&d_atl[gi] = *(uint4*)ls;
    }
}

// ---------------------------------------------------------------------------
// output GEMM via mma.sync: out[ch][tok] = wcomb[ch] . attn[tok] + bias
// Block tile: 128 tok x 64 ch; smem-staged transposed store.
// ---------------------------------------------------------------------------
__global__ __launch_bounds__(256) void out_mms(float* __restrict__ out) {
    __shared__ __align__(16) char smraw[34816];
    __nv_bfloat16 (*Ah)[40] = (__nv_bfloat16(*)[40])(smraw);
    __nv_bfloat16 (*Al)[40] = (__nv_bfloat16(*)[40])(smraw + 10240);
    __nv_bfloat16 (*Bh)[40] = (__nv_bfloat16(*)[40])(smraw + 20480);
    __nv_bfloat16 (*Bl)[40] = (__nv_bfloat16(*)[40])(smraw + 25600);
    float (*Ct)[132] = (float(*)[132])(smraw);

    int m0 = blockIdx.x * 128, n0 = blockIdx.y * 64;
    int tid = threadIdx.x, wid = tid >> 5, lane = tid & 31;
    int wm = (wid & 3) * 32, wn = (wid >> 2) * 32;

    float acc[2][4][4];
    #pragma unroll
    for (int mi = 0; mi < 2; mi++)
        #pragma unroll
        for (int ni = 0; ni < 4; ni++)
            #pragma unroll
            for (int q = 0; q < 4; q++) acc[mi][ni][q] = 0.0f;

    int arow = wm + (lane & 15);
    int acol8 = (lane >> 4) * 8;
    int brow = wn + ((lane >> 4) << 3) + (lane & 7);
    int bcol8 = ((lane >> 3) & 1) * 8;

    for (int ck = 0; ck < 8; ck++) {
        int k0 = ck * 32;
        #pragma unroll
        for (int j = 0; j < 2; j++) {
            int i = tid + j*256, row = i >> 2, cg = i & 3;
            size_t g = (size_t)(m0 + row)*CHN + k0 + cg*8;
            *(uint4*)&Ah[row][cg*8] = *(const uint4*)(d_ath + g);
            *(uint4*)&Al[row][cg*8] = *(const uint4*)(d_atl + g);
        }
        {
            int row = tid >> 2, cg = tid & 3;
            size_t g = (size_t)(n0 + row)*CHN + k0 + cg*8;
            *(uint4*)&Bh[row][cg*8] = *(const uint4*)(d_wch + g);
            *(uint4*)&Bl[row][cg*8] = *(const uint4*)(d_wcl + g);
        }
        __syncthreads();
        #pragma unroll
        for (int ks = 0; ks < 32; ks += 16) {
            uint32_t ah[2][4], al[2][4], bh[2][4], bl[2][4];
            #pragma unroll
            for (int mi = 0; mi < 2; mi++) {
                ldsm_x4(ah[mi], smem_u32(&Ah[arow + mi*16][ks + acol8]));
                ldsm_x4(al[mi], smem_u32(&Al[arow + mi*16][ks + acol8]));
            }
            #pragma unroll
            for (int p = 0; p < 2; p++) {
                ldsm_x4(bh[p], smem_u32(&Bh[brow + p*16][ks + bcol8]));
                ldsm_x4(bl[p], smem_u32(&Bl[brow + p*16][ks + bcol8]));
            }
            #pragma unroll
            for (int mi = 0; mi < 2; mi++)
                #pragma unroll
                for (int ni = 0; ni < 4; ni++) {
                    const uint32_t* bhp = &bh[ni >> 1][(ni & 1)*2];
                    const uint32_t* blp = &bl[ni >> 1][(ni & 1)*2];
                    mma16816(acc[mi][ni], ah[mi], bhp);
                    mma16816(acc[mi][ni], ah[mi], blp);
                    mma16816(acc[mi][ni], al[mi], bhp);
                }
        }
        __syncthreads();
    }

    // stage transposed: Ct[ch_local][tok_local]
    #pragma unroll
    for (int mi = 0; mi < 2; mi++)
        #pragma unroll
        for (int ni = 0; ni < 4; ni++) {
            int ml = wm + mi*16 + (lane >> 2);
            int nl = wn + ni*8 + 2*(lane & 3);
            Ct[nl][ml]       = acc[mi][ni][0];
            Ct[nl+1][ml]     = acc[mi][ni][1];
            Ct[nl][ml+8]     = acc[mi][ni][2];
            Ct[nl+1][ml+8]   = acc[mi][ni][3];
        }
    __syncthreads();

    int bb = m0 / NTOK, ptok = m0 % NTOK;
    int ch = tid >> 2, tg = tid & 3;
    float bias = d_bcomb[n0 + ch];
    size_t rowb = (size_t)(bb*CHN + n0 + ch) * NTOK + ptok;
    #pragma unroll
    for (int j = 0; j < 8; j++) {
        int tl = tg*32 + j*4;
        float4 v = *(float4*)&Ct[ch][tl];
        *(float4*)&out[rowb + tl] = make_float4(v.x+bias, v.y+bias, v.z+bias, v.w+bias);
    }
}

extern "C" void kernel_launch(void* const* d_in, const int* in_sizes, int n_in,
                              void* d_out, int out_size) {
    const float* x    = (const float*)d_in[0];
    const float* wq   = (const float*)d_in[1];
    const float* wk   = (const float*)d_in[2];
    const float* wv   = (const float*)d_in[3];
    const float* wo   = (const float*)d_in[4];
    const float* bo   = (const float*)d_in[5];
    const float* proj = (const float*)d_in[6];
    const float* wp   = (const float*)d_in[7];
    const float* bp   = (const float*)d_in[8];
    float* out = (float*)d_out;

    init_k<<<512, 256>>>();
    conv_w<<<dim3(256, 3), 256>>>(wq, wk, wv);
    wcomb_k<<<256, 256>>>(wo, bo, wp, bp);
    xt_k<<<dim3(288, 8, 4), 256>>>(x);
    qkv_mms<<<dim3(288, 4, 3), 256>>>();
    k_fused<<<dim3(32, BH), 256>>>(proj);
    k_final<<<BH, 128>>>();
    q_attn<<<dim3(288, BH), 128>>>(proj);
    out_mms<<<dim3(288, 4), 256>>>(out);
}